// round 4
// baseline (speedup 1.0000x reference)
#include <cuda_runtime.h>

// Exact analytical collapse of the reference (verified bit-exact in R1):
//   attention output is binary*[0,1] -> post-attn LIF never reaches V_TH=1
//   (v' = (v+x)/2 < 1 strictly for all 4 steps) -> all-zero spikes ->
//   pw @ 0 = 0 -> BN(0) = p_beta broadcast over [T,B,C,8,32,32].
//
// Output = p_beta[c] broadcast, c = (elem / 8192) % 128.
//
// R2 layout: 2^21 float4 total = 1024 planes x 2048 float4.
// One block per plane (channel uniform per block), 256 threads,
// 8 coalesced STG.128 per thread for deep store MLP.

static constexpr int PLANES      = 1024;   // T*B*C = 4*2*128
static constexpr int F4_PER_PLANE = 2048;  // 8192 floats / 4
static constexpr int THREADS     = 256;
static constexpr int F4_PER_THREAD = F4_PER_PLANE / THREADS;  // 8

__global__ __launch_bounds__(THREADS)
void bisda_broadcast_beta2(const float* __restrict__ p_beta,
                           float4* __restrict__ out) {
    const int b = blockIdx.x;            // plane index
    const int c = b & 127;               // channel (uniform per block)
    const float v = __ldg(p_beta + c);
    const float4 v4 = make_float4(v, v, v, v);

    float4* base = out + (size_t)b * F4_PER_PLANE + threadIdx.x;
#pragma unroll
    for (int k = 0; k < F4_PER_THREAD; ++k) {
        base[k * THREADS] = v4;          // 8 independent coalesced STG.128
    }
}

extern "C" void kernel_launch(void* const* d_in, const int* in_sizes, int n_in,
                              void* d_out, int out_size) {
    const float* p_beta = (const float*)d_in[11];
    float4* out = (float4*)d_out;
    bisda_broadcast_beta2<<<PLANES, THREADS>>>(p_beta, out);
}